// round 15
// baseline (speedup 1.0000x reference)
#include <cuda_runtime.h>
#include <cuda_bf16.h>
#include <math.h>
#include <cstdint>

// Problem constants (fixed shapes from the reference)
#define TOTAL_NODES 32768
#define BG   64
#define NN   512
#define VV   64
#define EE   1048576
#define INF_ 128
#define HH   256
#define OUTD 10
#define BUCKET 128   // fixed CSR bucket per node (avg deg 32, P(>128) ~ 0)

// ---------------- scratch (static device globals; no allocation) ----------------
__device__ float g_h  [TOTAL_NODES * HH];   // g (post-GCN)
__device__ float g_hw [TOTAL_NODES * HH];   // dinv-prescaled hw
__device__ float g_t  [TOTAL_NODES * HH];
__device__ float g_proto[BG * HH];
__device__ float g_pn [BG];
__device__ float g_mw [BG * NN * VV];
__device__ float g_vn [BG * VV * HH];
__device__ float g_vn3[BG * VV * HH];
__device__ int   g_cursor[TOTAL_NODES];
__device__ float g_dinv  [TOTAL_NODES];
__device__ int   g_csr   [TOTAL_NODES * BUCKET];   // 16 MB fixed-stride buckets
// pre-split transposed weights: 6 slots of [N,K] bf16 (slot stride 256*256)
__device__ __nv_bfloat16 g_wh[6 * 256 * 256];
__device__ __nv_bfloat16 g_wl[6 * 256 * 256];
// split intermediate scratch (h, t1, vn2 — sequential lifetimes)
__device__ __nv_bfloat16 g_sh[TOTAL_NODES * HH];
__device__ __nv_bfloat16 g_sl[TOTAL_NODES * HH];

// ---------------- bucket CSR build (no scan) ----------------
__global__ void zero_cursor_kernel() {
    int i = blockIdx.x * blockDim.x + threadIdx.x;
    if (i < TOTAL_NODES) g_cursor[i] = 0;
}

__global__ void fill_kernel(const int* __restrict__ src, const int* __restrict__ dst) {
    int e = blockIdx.x * blockDim.x + threadIdx.x;
    if (e < EE) {
        int d = dst[e];
        int p = atomicAdd(&g_cursor[d], 1);
        g_csr[d * BUCKET + p] = src[e];
    }
}

__global__ void dinv_kernel() {
    int i = blockIdx.x * blockDim.x + threadIdx.x;
    if (i < TOTAL_NODES) g_dinv[i] = rsqrtf(1.0f + (float)g_cursor[i]);
}

// ---------------- fused weight split+transpose: all 6 weights in one launch ----------------
__global__ void split_all_kernel(const float* __restrict__ w0, const float* __restrict__ w1,
                                 const float* __restrict__ w2, const float* __restrict__ w3,
                                 const float* __restrict__ w4, const float* __restrict__ w5) {
    int slot = blockIdx.y;
    const float* W;
    switch (slot) {
        case 0: W = w0; break; case 1: W = w1; break; case 2: W = w2; break;
        case 3: W = w3; break; case 4: W = w4; break; default: W = w5; break;
    }
    int K = (slot == 0) ? INF_ : HH;
    int idx = blockIdx.x * 256 + threadIdx.x;
    if (idx >= K * HH) return;
    int k = idx / HH, n = idx % HH;
    float v = W[idx];
    __nv_bfloat16 hb = __float2bfloat16_rn(v);
    float r = v - __bfloat162float(hb);
    size_t o = (size_t)slot * (256 * 256) + (size_t)n * K + k;
    g_wh[o] = hb;
    g_wl[o] = __float2bfloat16_rn(r);
}

// ---------------- mma.sync bf16-split GEMM ----------------
// 64(M) x 128(N) CTA tile, BK=32, 8 warps (2x4), warp tile 32x32.
// Double-buffered, cp.async, ldmatrix fragments, 3 CTAs/SM.
// SCALE: multiply output row r by g_dinv[r].
// ASPLIT: A pre-split bf16 (Ah_g/Al_g), loaded via cp.async. Else fp32 A, loader split.
// OSPLIT: write hi/lo bf16 split to Ch/Cl instead of fp32 C.
#define MMA_BF16(d, a, b) \
    asm volatile("mma.sync.aligned.m16n8k16.row.col.f32.bf16.bf16.f32 " \
        "{%0,%1,%2,%3}, {%4,%5,%6,%7}, {%8,%9}, {%0,%1,%2,%3};" \
        : "+f"((d)[0]), "+f"((d)[1]), "+f"((d)[2]), "+f"((d)[3]) \
        : "r"((a)[0]), "r"((a)[1]), "r"((a)[2]), "r"((a)[3]), "r"((b)[0]), "r"((b)[1]))

#define LDSM4(r0, r1, r2, r3, addr) \
    asm volatile("ldmatrix.sync.aligned.m8n8.x4.shared.b16 {%0,%1,%2,%3}, [%4];" \
        : "=r"(r0), "=r"(r1), "=r"(r2), "=r"(r3) : "r"(addr))

#define APITCH 80                     // bytes per 32-bf16 row (64B data + 16B pad)
#define A_TILE (64 * APITCH)          // 5120
#define B_TILE (128 * APITCH)         // 10240
#define BUF_BYTES (2 * A_TILE + 2 * B_TILE)   // 30720: Ah, Al, Bh, Bl
#define OFF_AL  A_TILE
#define OFF_BH  (2 * A_TILE)
#define OFF_BL  (2 * A_TILE + B_TILE)
#define GEMM_SMEM (2 * BUF_BYTES)     // 61440

__device__ __forceinline__ uint32_t smem_u32(const void* p) {
    uint32_t a;
    asm("{ .reg .u64 t; cvta.to.shared.u64 t, %1; cvt.u32.u64 %0, t; }" : "=r"(a) : "l"(p));
    return a;
}
#define CP_ASYNC16(saddr, gptr) \
    asm volatile("cp.async.cg.shared.global [%0], [%1], 16;" :: "r"(saddr), "l"(gptr))
#define CP_COMMIT() asm volatile("cp.async.commit_group;" ::: "memory")
#define CP_WAIT0()  asm volatile("cp.async.wait_group 0;" ::: "memory")

__device__ __forceinline__ uint32_t pack_split_hi(float a, float b,
                                                  __nv_bfloat16& ha, __nv_bfloat16& hb) {
    ha = __float2bfloat16_rn(a);
    hb = __float2bfloat16_rn(b);
    return (uint32_t)__bfloat16_as_ushort(ha) | ((uint32_t)__bfloat16_as_ushort(hb) << 16);
}
__device__ __forceinline__ uint32_t pack_lo(float a, float b, __nv_bfloat16 ha, __nv_bfloat16 hb) {
    __nv_bfloat16 la = __float2bfloat16_rn(a - __bfloat162float(ha));
    __nv_bfloat16 lb = __float2bfloat16_rn(b - __bfloat162float(hb));
    return (uint32_t)__bfloat16_as_ushort(la) | ((uint32_t)__bfloat16_as_ushort(lb) << 16);
}

template<bool RELU, bool BIAS, bool SCALE, bool ASPLIT, bool OSPLIT>
__global__ void __launch_bounds__(256, 3) gemm_mma_kernel(
    const float* __restrict__ A,
    const __nv_bfloat16* __restrict__ Ah_g, const __nv_bfloat16* __restrict__ Al_g,
    const __nv_bfloat16* __restrict__ Bh, const __nv_bfloat16* __restrict__ Bl,
    const float* __restrict__ bias, float* __restrict__ C,
    __nv_bfloat16* __restrict__ Ch, __nv_bfloat16* __restrict__ Cl,
    int M, int N, int K)
{
    extern __shared__ char smem[];
    const uint32_t sb32 = smem_u32(smem);

    const int tid = threadIdx.x;
    const int wid = tid >> 5, lane = tid & 31;
    const int warp_m = wid & 1;       // 2 x 32 rows
    const int warp_n = wid >> 1;      // 4 x 32 cols
    const int row0 = blockIdx.y * 64, col0 = blockIdx.x * 128;

    const int mat = lane >> 3, r8 = lane & 7;
    const uint32_t aoff = (uint32_t)((warp_m * 32 + (mat & 1) * 8 + r8) * APITCH + (mat >> 1) * 16);
    const uint32_t boff = (uint32_t)((warp_n * 32 + (mat >> 1) * 8 + r8) * APITCH + (mat & 1) * 16);

    float acc[2][4][4];
#pragma unroll
    for (int i = 0; i < 2; i++)
#pragma unroll
        for (int j = 0; j < 4; j++)
#pragma unroll
            for (int q = 0; q < 4; q++) acc[i][j][q] = 0.f;

    const int nk = K >> 5;
    float4 pa[2];

    auto ldg_A = [&](int kc) {
#pragma unroll
        for (int it = 0; it < 2; it++) {
            int i = tid + it * 256;
            int r = i >> 3, kq = i & 7;
            pa[it] = *(const float4*)(A + (size_t)(row0 + r) * K + kc + kq * 4);
        }
    };
    auto sts_A = [&](int bb) {
        char* dAh = smem + bb * BUF_BYTES;
        char* dAl = dAh + OFF_AL;
#pragma unroll
        for (int it = 0; it < 2; it++) {
            int i = tid + it * 256;
            int r = i >> 3, kq = i & 7;
            float4 v = pa[it];
            __nv_bfloat16 h0, h1, h2, h3;
            uint2 uh, ul;
            uh.x = pack_split_hi(v.x, v.y, h0, h1);
            uh.y = pack_split_hi(v.z, v.w, h2, h3);
            ul.x = pack_lo(v.x, v.y, h0, h1);
            ul.y = pack_lo(v.z, v.w, h2, h3);
            *(uint2*)(dAh + r * APITCH + kq * 8) = uh;
            *(uint2*)(dAl + r * APITCH + kq * 8) = ul;
        }
    };
    auto cpasync_A = [&](int kc, int bb) {   // ASPLIT path: 256 quads per matrix
        uint32_t dAh = sb32 + bb * BUF_BYTES;
        uint32_t dAl = dAh + OFF_AL;
        int r = tid >> 2, kq = tid & 3;
        size_t goff = (size_t)(row0 + r) * K + kc + kq * 8;
        CP_ASYNC16(dAh + r * APITCH + kq * 16, Ah_g + goff);
        CP_ASYNC16(dAl + r * APITCH + kq * 16, Al_g + goff);
    };
    auto cpasync_B = [&](int kc, int bb) {
        uint32_t dBh = sb32 + bb * BUF_BYTES + OFF_BH;
        uint32_t dBl = sb32 + bb * BUF_BYTES + OFF_BL;
#pragma unroll
        for (int it = 0; it < 2; it++) {
            int i = tid + it * 256;
            int n = i >> 2, kq = i & 3;
            size_t goff = (size_t)(col0 + n) * K + kc + kq * 8;
            CP_ASYNC16(dBh + n * APITCH + kq * 16, Bh + goff);
            CP_ASYNC16(dBl + n * APITCH + kq * 16, Bl + goff);
        }
    };
    auto stage = [&](int kc, int bb) {
        if (ASPLIT) cpasync_A(kc, bb);
        cpasync_B(kc, bb);
        CP_COMMIT();
    };

    // prologue
    if (!ASPLIT) ldg_A(0);
    stage(0, 0);
    if (!ASPLIT) sts_A(0);
    CP_WAIT0();
    __syncthreads();

    int buf = 0;
    for (int c = 0; c < nk; c++) {
        if (c + 1 < nk) {
            if (!ASPLIT) ldg_A((c + 1) << 5);
            stage((c + 1) << 5, buf ^ 1);
        }

        const uint32_t base = sb32 + buf * BUF_BYTES;
#pragma unroll
        for (int ks = 0; ks < 2; ks++) {
            const int kb = ks * 32;
            uint32_t ah[2][4], al[2][4];
            LDSM4(ah[0][0], ah[0][1], ah[0][2], ah[0][3], base + aoff + kb);
            LDSM4(ah[1][0], ah[1][1], ah[1][2], ah[1][3], base + aoff + kb + 16 * APITCH);
            LDSM4(al[0][0], al[0][1], al[0][2], al[0][3], base + OFF_AL + aoff + kb);
            LDSM4(al[1][0], al[1][1], al[1][2], al[1][3], base + OFF_AL + aoff + kb + 16 * APITCH);
#pragma unroll
            for (int p = 0; p < 2; p++) {
                uint32_t bq = base + OFF_BH + boff + kb + p * 16 * APITCH;
                uint32_t bhv[4], blv[4];
                LDSM4(bhv[0], bhv[1], bhv[2], bhv[3], bq);
                LDSM4(blv[0], blv[1], blv[2], blv[3], bq + B_TILE);
#pragma unroll
                for (int sub = 0; sub < 2; sub++) {
                    uint32_t bh2[2] = {bhv[2 * sub], bhv[2 * sub + 1]};
                    uint32_t bl2[2] = {blv[2 * sub], blv[2 * sub + 1]};
                    const int nt = 2 * p + sub;
#pragma unroll
                    for (int mt = 0; mt < 2; mt++) {
                        MMA_BF16(acc[mt][nt], ah[mt], bh2);
                        MMA_BF16(acc[mt][nt], ah[mt], bl2);
                        MMA_BF16(acc[mt][nt], al[mt], bh2);
                    }
                }
            }
        }

        if (c + 1 < nk) {
            if (!ASPLIT) sts_A(buf ^ 1);
            CP_WAIT0();
        }
        __syncthreads();
        buf ^= 1;
    }

    // epilogue
#pragma unroll
    for (int mt = 0; mt < 2; mt++) {
        int r0 = row0 + warp_m * 32 + mt * 16 + (lane >> 2);
        float s0 = 1.f, s1 = 1.f;
        if (SCALE) { s0 = g_dinv[r0]; s1 = g_dinv[r0 + 8]; }
#pragma unroll
        for (int nt = 0; nt < 4; nt++) {
            int c = col0 + warp_n * 32 + nt * 8 + (lane & 3) * 2;
            float v0 = acc[mt][nt][0], v1 = acc[mt][nt][1];
            float v2 = acc[mt][nt][2], v3 = acc[mt][nt][3];
            if (BIAS) {
                float b0 = bias[c], b1 = bias[c + 1];
                v0 += b0; v1 += b1; v2 += b0; v3 += b1;
            }
            if (SCALE) { v0 *= s0; v1 *= s0; v2 *= s1; v3 *= s1; }
            if (RELU) {
                v0 = fmaxf(v0, 0.f); v1 = fmaxf(v1, 0.f);
                v2 = fmaxf(v2, 0.f); v3 = fmaxf(v3, 0.f);
            }
            if (OSPLIT) {
                __nv_bfloat16 h0, h1, h2, h3;
                uint32_t uh01 = pack_split_hi(v0, v1, h0, h1);
                uint32_t uh23 = pack_split_hi(v2, v3, h2, h3);
                uint32_t ul01 = pack_lo(v0, v1, h0, h1);
                uint32_t ul23 = pack_lo(v2, v3, h2, h3);
                *(uint32_t*)(Ch + (size_t)r0 * N + c) = uh01;
                *(uint32_t*)(Cl + (size_t)r0 * N + c) = ul01;
                *(uint32_t*)(Ch + (size_t)(r0 + 8) * N + c) = uh23;
                *(uint32_t*)(Cl + (size_t)(r0 + 8) * N + c) = ul23;
            } else {
                *(float2*)(C + (size_t)r0 * N + c) = make_float2(v0, v1);
                *(float2*)(C + (size_t)(r0 + 8) * N + c) = make_float2(v2, v3);
            }
        }
    }
}

// ---------------- vn mma GEMM: vn[b] = mw[b]^T (64x512) @ g[b] (512x256) ----------------
__global__ void __launch_bounds__(256) vn_mma_kernel(
    const float* __restrict__ mw, const float* __restrict__ gfeat, float* __restrict__ vn)
{
    __shared__ __align__(16) char sAh[64 * APITCH];
    __shared__ __align__(16) char sAl[64 * APITCH];
    __shared__ __align__(16) char sBh[128 * APITCH];
    __shared__ __align__(16) char sBl[128 * APITCH];

    const int b = blockIdx.y;
    const int col0 = blockIdx.x * 128;
    const float* mwb = mw + (size_t)b * NN * VV;
    const float* gb  = gfeat + (size_t)b * NN * HH;
    float* vnb = vn + (size_t)b * VV * HH;

    const int tid = threadIdx.x;
    const int wid = tid >> 5, lane = tid & 31;
    const int warp_m = wid & 1;
    const int warp_n = wid >> 1;
    const int lr = lane >> 2;
    const int lk4 = (lane & 3) * 4;

    float acc[2][4][4];
#pragma unroll
    for (int i = 0; i < 2; i++)
#pragma unroll
        for (int j = 0; j < 4; j++)
#pragma unroll
            for (int q = 0; q < 4; q++) acc[i][j][q] = 0.f;

    for (int kc = 0; kc < NN; kc += 32) {
#pragma unroll
        for (int it = 0; it < 4; it++) {
            int i = tid + it * 256;
            int v = i & 63, kp = i >> 6;
            float x0 = mwb[(size_t)(kc + 2 * kp) * VV + v];
            float x1 = mwb[(size_t)(kc + 2 * kp + 1) * VV + v];
            __nv_bfloat16 h0, h1;
            uint32_t uh = pack_split_hi(x0, x1, h0, h1);
            uint32_t ul = pack_lo(x0, x1, h0, h1);
            *(uint32_t*)(sAh + v * APITCH + kp * 4) = uh;
            *(uint32_t*)(sAl + v * APITCH + kp * 4) = ul;
        }
#pragma unroll
        for (int it = 0; it < 8; it++) {
            int i = tid + it * 256;
            int n = i & 127, kp = i >> 7;
            float x0 = gb[(size_t)(kc + 2 * kp) * HH + col0 + n];
            float x1 = gb[(size_t)(kc + 2 * kp + 1) * HH + col0 + n];
            __nv_bfloat16 h0, h1;
            uint32_t uh = pack_split_hi(x0, x1, h0, h1);
            uint32_t ul = pack_lo(x0, x1, h0, h1);
            *(uint32_t*)(sBh + n * APITCH + kp * 4) = uh;
            *(uint32_t*)(sBl + n * APITCH + kp * 4) = ul;
        }
        __syncthreads();

#pragma unroll
        for (int ks = 0; ks < 2; ks++) {
            const int kb = ks * 32;
            uint32_t ah[2][4], al[2][4];
#pragma unroll
            for (int mt = 0; mt < 2; mt++) {
                const char* base = sAh + (warp_m * 32 + mt * 16 + lr) * APITCH + kb + lk4;
                ah[mt][0] = *(const uint32_t*)base;
                ah[mt][1] = *(const uint32_t*)(base + 8 * APITCH);
                ah[mt][2] = *(const uint32_t*)(base + 16);
                ah[mt][3] = *(const uint32_t*)(base + 8 * APITCH + 16);
                const char* basel = sAl + (warp_m * 32 + mt * 16 + lr) * APITCH + kb + lk4;
                al[mt][0] = *(const uint32_t*)basel;
                al[mt][1] = *(const uint32_t*)(basel + 8 * APITCH);
                al[mt][2] = *(const uint32_t*)(basel + 16);
                al[mt][3] = *(const uint32_t*)(basel + 8 * APITCH + 16);
            }
#pragma unroll
            for (int nt = 0; nt < 4; nt++) {
                const char* bbase = sBh + (warp_n * 32 + nt * 8 + lr) * APITCH + kb + lk4;
                uint32_t bh[2], bl[2];
                bh[0] = *(const uint32_t*)bbase;
                bh[1] = *(const uint32_t*)(bbase + 16);
                const char* bbl = sBl + (warp_n * 32 + nt * 8 + lr) * APITCH + kb + lk4;
                bl[0] = *(const uint32_t*)bbl;
                bl[1] = *(const uint32_t*)(bbl + 16);
#pragma unroll
                for (int mt = 0; mt < 2; mt++) {
                    MMA_BF16(acc[mt][nt], ah[mt], bh);
                    MMA_BF16(acc[mt][nt], ah[mt], bl);
                    MMA_BF16(acc[mt][nt], al[mt], bh);
                }
            }
        }
        __syncthreads();
    }

#pragma unroll
    for (int mt = 0; mt < 2; mt++) {
        int r0 = warp_m * 32 + mt * 16 + lr;
#pragma unroll
        for (int nt = 0; nt < 4; nt++) {
            int c = col0 + warp_n * 32 + nt * 8 + (lane & 3) * 2;
            *(float2*)(vnb + (size_t)r0 * HH + c) = make_float2(acc[mt][nt][0], acc[mt][nt][1]);
            *(float2*)(vnb + (size_t)(r0 + 8) * HH + c) = make_float2(acc[mt][nt][2], acc[mt][nt][3]);
        }
    }
}

// ---------------- GCN gather (bucket CSR, prescaled hw, MLP=4) + scale + bias + relu ----------------
__global__ void gather_gcn_kernel(const float* __restrict__ bgcn) {
    int node = blockIdx.x * 4 + threadIdx.y;
    int t = threadIdx.x;              // 0..63
    const float4* hw4 = (const float4*)g_hw;    // prescaled by dinv[row]
    const int* csr = g_csr + node * BUCKET;
    int deg = g_cursor[node];
    float di = g_dinv[node];
    float4 acc = make_float4(0.f, 0.f, 0.f, 0.f);
    int e = 0;
    for (; e + 4 <= deg; e += 4) {
        int s0 = csr[e], s1 = csr[e + 1], s2 = csr[e + 2], s3 = csr[e + 3];
        float4 v0 = hw4[(size_t)s0 * 64 + t];
        float4 v1 = hw4[(size_t)s1 * 64 + t];
        float4 v2 = hw4[(size_t)s2 * 64 + t];
        float4 v3 = hw4[(size_t)s3 * 64 + t];
        acc.x += v0.x + v1.x + v2.x + v3.x;
        acc.y += v0.y + v1.y + v2.y + v3.y;
        acc.z += v0.z + v1.z + v2.z + v3.z;
        acc.w += v0.w + v1.w + v2.w + v3.w;
    }
    for (; e < deg; e++) {
        int s = csr[e];
        float4 v = hw4[(size_t)s * 64 + t];
        acc.x += v.x; acc.y += v.y; acc.z += v.z; acc.w += v.w;
    }
    float4 vs = hw4[(size_t)node * 64 + t];
    acc.x = (acc.x + vs.x) * di;
    acc.y = (acc.y + vs.y) * di;
    acc.z = (acc.z + vs.z) * di;
    acc.w = (acc.w + vs.w) * di;
    float4 bb = ((const float4*)bgcn)[t];
    acc.x = fmaxf(acc.x + bb.x, 0.f);
    acc.y = fmaxf(acc.y + bb.y, 0.f);
    acc.z = fmaxf(acc.z + bb.z, 0.f);
    acc.w = fmaxf(acc.w + bb.w, 0.f);
    ((float4*)g_h)[(size_t)node * 64 + t] = acc;
}

// ---------------- proto = mean_n t, pn = ||proto|| ----------------
__global__ void proto_kernel() {
    int b = blockIdx.x;
    int h = threadIdx.x;   // 256
    const float* tb = g_t + (size_t)b * NN * HH;
    float s = 0.f;
    for (int n = 0; n < NN; n++) s += tb[(size_t)n * HH + h];
    s *= (1.0f / NN);
    g_proto[b * HH + h] = s;
    __shared__ float red[256];
    red[h] = s * s;
    __syncthreads();
    for (int off = 128; off > 0; off >>= 1) {
        if (h < off) red[h] += red[h + off];
        __syncthreads();
    }
    if (h == 0) g_pn[b] = fmaxf(sqrtf(red[0]), 1e-8f);
}

// ---------------- fused attention + mw (warp per node) ----------------
__global__ void att_mw_kernel(const float* __restrict__ ew) {
    int w = (blockIdx.x * blockDim.x + threadIdx.x) >> 5;
    int lane = threadIdx.x & 31;
    if (w >= TOTAL_NODES) return;
    int b = w >> 9;
    const float* tr = g_t + (size_t)w * HH;
    const float* pr = g_proto + b * HH;
    float dot = 0.f, nrm = 0.f;
    for (int j = lane; j < HH; j += 32) {
        float v = tr[j];
        dot += v * pr[j];
        nrm += v * v;
    }
#pragma unroll
    for (int off = 16; off; off >>= 1) {
        dot += __shfl_xor_sync(0xffffffffu, dot, off);
        nrm += __shfl_xor_sync(0xffffffffu, nrm, off);
    }
    float tn = fmaxf(sqrtf(nrm), 1e-8f);
    float sim = dot / (tn * g_pn[b]);
    float a = 0.5f * (1.0f + sim);

    const float* e = ew + (size_t)w * VV;
    float v0 = e[lane] * a;
    float v1 = e[lane + 32] * a;
    float rs = v0 + v1;
#pragma unroll
    for (int off = 16; off; off >>= 1) rs += __shfl_xor_sync(0xffffffffu, rs, off);
    float sc = (rs == 0.0f) ? 1.0f : (1.0f / rs);
    float* m = g_mw + (size_t)w * VV;
    m[lane]      = v0 * sc;
    m[lane + 32] = v1 * sc;
}

// ---------------- fused readout ----------------
__global__ void __launch_bounds__(256) readout_kernel(
    const float* __restrict__ mW1, const float* __restrict__ mb1,
    const float* __restrict__ mW2, const float* __restrict__ mb2,
    float* __restrict__ out)
{
    __shared__ float sgf[HH];
    __shared__ float sm1[HH];
    const int b = blockIdx.x, h = threadIdx.x;

    const float* v = g_vn3 + (size_t)b * VV * HH;
    float s = 0.f;
#pragma unroll 8
    for (int i = 0; i < VV; i++) s += v[i * HH + h];
    sgf[h] = s * (1.0f / VV);
    __syncthreads();

    float acc = mb1[h];
    for (int k = 0; k < HH; k++) acc += sgf[k] * mW1[(size_t)k * HH + h];
    sm1[h] = fmaxf(acc, 0.f);
    __syncthreads();

    if (h < OUTD) {
        float o = mb2[h];
        for (int k = 0; k < HH; k++) o += sm1[k] * mW2[(size_t)k * OUTD + h];
        out[b * OUTD + h] = o;
    }
}

// ---------------- launch ----------------
extern "C" void kernel_launch(void* const* d_in, const int* in_sizes, int n_in,
                              void* d_out, int out_size)
{
    const float* x     = (const float*)d_in[0];
    const int*   esrc  = (const int*)  d_in[1];
    const int*   edst  = (const int*)  d_in[2];
    const float* W_emb = (const float*)d_in[3];
    const float* b_emb = (const float*)d_in[4];
    const float* W_gcn = (const float*)d_in[5];
    const float* b_gcn = (const float*)d_in[6];
    const float* aW1   = (const float*)d_in[7];
    const float* ab1   = (const float*)d_in[8];
    const float* aW2   = (const float*)d_in[9];
    const float* ab2   = (const float*)d_in[10];
    const float* vW1   = (const float*)d_in[11];
    const float* vb1   = (const float*)d_in[12];
    const float* vW2   = (const float*)d_in[13];
    const float* vb2   = (const float*)d_in[14];
    const float* mW1   = (const float*)d_in[15];
    const float* mb1   = (const float*)d_in[16];
    const float* mW2   = (const float*)d_in[17];
    const float* mb2   = (const float*)d_in[18];
    const float* ew    = (const float*)d_in[19];
    float* out = (float*)d_out;

    float *h, *hw, *t, *mw, *vn, *vn3;
    __nv_bfloat16 *wh, *wl, *sh, *sl;
    cudaGetSymbolAddress((void**)&h,   g_h);
    cudaGetSymbolAddress((void**)&hw,  g_hw);
    cudaGetSymbolAddress((void**)&t,   g_t);
    cudaGetSymbolAddress((void**)&mw,  g_mw);
    cudaGetSymbolAddress((void**)&vn,  g_vn);
    cudaGetSymbolAddress((void**)&vn3, g_vn3);
    cudaGetSymbolAddress((void**)&wh,  g_wh);
    cudaGetSymbolAddress((void**)&wl,  g_wl);
    cudaGetSymbolAddress((void**)&sh,  g_sh);
    cudaGetSymbolAddress((void**)&sl,  g_sl);

    static bool attr_done = false;
    if (!attr_done) {
        cudaFuncSetAttribute(gemm_mma_kernel<false, true,  false, false, true>,  cudaFuncAttributeMaxDynamicSharedMemorySize, GEMM_SMEM);
        cudaFuncSetAttribute(gemm_mma_kernel<false, false, true,  true,  false>, cudaFuncAttributeMaxDynamicSharedMemorySize, GEMM_SMEM);
        cudaFuncSetAttribute(gemm_mma_kernel<true,  true,  false, false, true>,  cudaFuncAttributeMaxDynamicSharedMemorySize, GEMM_SMEM);
        cudaFuncSetAttribute(gemm_mma_kernel<false, true,  false, true,  false>, cudaFuncAttributeMaxDynamicSharedMemorySize, GEMM_SMEM);
        attr_done = true;
    }

    const int WS = 256 * 256;   // weight slot stride

    // launches 1-3
    split_all_kernel<<<dim3(256, 6), 256>>>(W_emb, W_gcn, aW1, aW2, vW1, vW2);
    zero_cursor_kernel<<<TOTAL_NODES / 256, 256>>>();
    fill_kernel<<<EE / 256, 256>>>(esrc, edst);

    // launch 4: G1 emb: h(split) = x @ W_emb + b_emb  (profiler lands here)
    gemm_mma_kernel<false, true, false, false, true><<<dim3(HH / 128, TOTAL_NODES / 64), 256, GEMM_SMEM>>>(
        x, nullptr, nullptr, wh + 0 * WS, wl + 0 * WS, b_emb, nullptr, sh, sl,
        TOTAL_NODES, HH, INF_);

    dinv_kernel<<<TOTAL_NODES / 256, 256>>>();

    // G2: hw = (h @ W_gcn) * dinv[row]   (A pre-split)
    gemm_mma_kernel<false, false, true, true, false><<<dim3(HH / 128, TOTAL_NODES / 64), 256, GEMM_SMEM>>>(
        nullptr, sh, sl, wh + 1 * WS, wl + 1 * WS, nullptr, hw, nullptr, nullptr,
        TOTAL_NODES, HH, HH);
    // gather: g = relu(dinv_d * (sum + self) + b_gcn)
    gather_gcn_kernel<<<TOTAL_NODES / 4, dim3(64, 4)>>>(b_gcn);

    // G3: t1(split) = relu(g @ aW1 + ab1)
    gemm_mma_kernel<true, true, false, false, true><<<dim3(HH / 128, TOTAL_NODES / 64), 256, GEMM_SMEM>>>(
        h, nullptr, nullptr, wh + 2 * WS, wl + 2 * WS, ab1, nullptr, sh, sl,
        TOTAL_NODES, HH, HH);
    // G4: t = t1 @ aW2 + ab2   (A pre-split)
    gemm_mma_kernel<false, true, false, true, false><<<dim3(HH / 128, TOTAL_NODES / 64), 256, GEMM_SMEM>>>(
        nullptr, sh, sl, wh + 3 * WS, wl + 3 * WS, ab2, t, nullptr, nullptr,
        TOTAL_NODES, HH, HH);

    // attention
    proto_kernel<<<BG, 256>>>();
    att_mw_kernel<<<TOTAL_NODES * 32 / 256, 256>>>(ew);

    // vn = mw^T @ g, then vn MLP with split chain
    vn_mma_kernel<<<dim3(2, BG), 256>>>(mw, h, vn);
    // G5: vn2(split) = relu(vn @ vW1 + vb1)
    gemm_mma_kernel<true, true, false, false, true><<<dim3(HH / 128, BG * VV / 64), 256, GEMM_SMEM>>>(
        vn, nullptr, nullptr, wh + 4 * WS, wl + 4 * WS, vb1, nullptr, sh, sl,
        BG * VV, HH, HH);
    // G6: vn3 = vn2 @ vW2 + vb2   (A pre-split)
    gemm_mma_kernel<false, true, false, true, false><<<dim3(HH / 128, BG * VV / 64), 256, GEMM_SMEM>>>(
        nullptr, sh, sl, wh + 5 * WS, wl + 5 * WS, vb2, vn3, nullptr, nullptr,
        BG * VV, HH, HH);

    // fused readout
    readout_kernel<<<BG, 256>>>(mW1, mb1, mW2, mb2, out);
}

// round 16
// speedup vs baseline: 1.0467x; 1.0467x over previous
#include <cuda_runtime.h>
#include <cuda_bf16.h>
#include <math.h>
#include <cstdint>

// Problem constants (fixed shapes from the reference)
#define TOTAL_NODES 32768
#define BG   64
#define NN   512
#define VV   64
#define EE   1048576
#define INF_ 128
#define HH   256
#define OUTD 10
#define BUCKET 128   // fixed CSR bucket per node (avg deg 32, P(>128) ~ 0)

// ---------------- scratch (static device globals; no allocation) ----------------
__device__ float g_h  [TOTAL_NODES * HH];   // g (post-GCN)
__device__ float g_hw [TOTAL_NODES * HH];   // dinv-prescaled hw
__device__ float g_t1 [TOTAL_NODES * HH];
__device__ float g_t  [TOTAL_NODES * HH];
__device__ float g_proto[BG * HH];          // accumulates sums, then mean in-place
__device__ float g_pn [BG];
__device__ float g_mw [BG * NN * VV];
__device__ float g_vn [BG * VV * HH];
__device__ float g_vn2[BG * VV * HH];
__device__ float g_vn3[BG * VV * HH];
__device__ int   g_cursor[TOTAL_NODES];
__device__ float g_dinv  [TOTAL_NODES];
__device__ int   g_csr   [TOTAL_NODES * BUCKET];   // 16 MB fixed-stride buckets
// pre-split transposed weights: 6 slots of [N,K] bf16 (slot stride 256*256)
__device__ __nv_bfloat16 g_wh[6 * 256 * 256];
__device__ __nv_bfloat16 g_wl[6 * 256 * 256];

// ---------------- bucket CSR build (no scan) + proto zero ----------------
__global__ void zero_cursor_kernel() {
    int i = blockIdx.x * blockDim.x + threadIdx.x;
    if (i < TOTAL_NODES) g_cursor[i] = 0;
    if (i < BG * HH) g_proto[i] = 0.f;
}

__global__ void fill_kernel(const int* __restrict__ src, const int* __restrict__ dst) {
    int e = blockIdx.x * blockDim.x + threadIdx.x;
    if (e < EE) {
        int d = dst[e];
        int p = atomicAdd(&g_cursor[d], 1);
        g_csr[d * BUCKET + p] = src[e];
    }
}

__global__ void dinv_kernel() {
    int i = blockIdx.x * blockDim.x + threadIdx.x;
    if (i < TOTAL_NODES) g_dinv[i] = rsqrtf(1.0f + (float)g_cursor[i]);
}

// ---------------- fused weight split+transpose: all 6 weights in one launch ----------------
__global__ void split_all_kernel(const float* __restrict__ w0, const float* __restrict__ w1,
                                 const float* __restrict__ w2, const float* __restrict__ w3,
                                 const float* __restrict__ w4, const float* __restrict__ w5) {
    int slot = blockIdx.y;
    const float* W;
    switch (slot) {
        case 0: W = w0; break; case 1: W = w1; break; case 2: W = w2; break;
        case 3: W = w3; break; case 4: W = w4; break; default: W = w5; break;
    }
    int K = (slot == 0) ? INF_ : HH;
    int idx = blockIdx.x * 256 + threadIdx.x;
    if (idx >= K * HH) return;
    int k = idx / HH, n = idx % HH;
    float v = W[idx];
    __nv_bfloat16 hb = __float2bfloat16_rn(v);
    float r = v - __bfloat162float(hb);
    size_t o = (size_t)slot * (256 * 256) + (size_t)n * K + k;
    g_wh[o] = hb;
    g_wl[o] = __float2bfloat16_rn(r);
}

// ---------------- mma.sync bf16-split GEMM ----------------
// 64(M) x 128(N) CTA tile, BK=32, 8 warps (2x4), warp tile 32x32.
// Double-buffered, cp.async for B, ldmatrix fragments, 3 CTAs/SM.
// SCALE: multiply output row r by g_dinv[r] (for GCN prescale).
#define MMA_BF16(d, a, b) \
    asm volatile("mma.sync.aligned.m16n8k16.row.col.f32.bf16.bf16.f32 " \
        "{%0,%1,%2,%3}, {%4,%5,%6,%7}, {%8,%9}, {%0,%1,%2,%3};" \
        : "+f"((d)[0]), "+f"((d)[1]), "+f"((d)[2]), "+f"((d)[3]) \
        : "r"((a)[0]), "r"((a)[1]), "r"((a)[2]), "r"((a)[3]), "r"((b)[0]), "r"((b)[1]))

#define LDSM4(r0, r1, r2, r3, addr) \
    asm volatile("ldmatrix.sync.aligned.m8n8.x4.shared.b16 {%0,%1,%2,%3}, [%4];" \
        : "=r"(r0), "=r"(r1), "=r"(r2), "=r"(r3) : "r"(addr))

#define APITCH 80                     // bytes per 32-bf16 row (64B data + 16B pad)
#define A_TILE (64 * APITCH)          // 5120
#define B_TILE (128 * APITCH)         // 10240
#define BUF_BYTES (2 * A_TILE + 2 * B_TILE)   // 30720: Ah, Al, Bh, Bl
#define OFF_AL  A_TILE
#define OFF_BH  (2 * A_TILE)
#define OFF_BL  (2 * A_TILE + B_TILE)
#define GEMM_SMEM (2 * BUF_BYTES)     // 61440

__device__ __forceinline__ uint32_t smem_u32(const void* p) {
    uint32_t a;
    asm("{ .reg .u64 t; cvta.to.shared.u64 t, %1; cvt.u32.u64 %0, t; }" : "=r"(a) : "l"(p));
    return a;
}
#define CP_ASYNC16(saddr, gptr) \
    asm volatile("cp.async.cg.shared.global [%0], [%1], 16;" :: "r"(saddr), "l"(gptr))
#define CP_COMMIT() asm volatile("cp.async.commit_group;" ::: "memory")
#define CP_WAIT0()  asm volatile("cp.async.wait_group 0;" ::: "memory")

__device__ __forceinline__ uint32_t pack_split_hi(float a, float b,
                                                  __nv_bfloat16& ha, __nv_bfloat16& hb) {
    ha = __float2bfloat16_rn(a);
    hb = __float2bfloat16_rn(b);
    return (uint32_t)__bfloat16_as_ushort(ha) | ((uint32_t)__bfloat16_as_ushort(hb) << 16);
}
__device__ __forceinline__ uint32_t pack_lo(float a, float b, __nv_bfloat16 ha, __nv_bfloat16 hb) {
    __nv_bfloat16 la = __float2bfloat16_rn(a - __bfloat162float(ha));
    __nv_bfloat16 lb = __float2bfloat16_rn(b - __bfloat162float(hb));
    return (uint32_t)__bfloat16_as_ushort(la) | ((uint32_t)__bfloat16_as_ushort(lb) << 16);
}

template<bool RELU, bool BIAS, bool SCALE>
__global__ void __launch_bounds__(256, 3) gemm_mma_kernel(
    const float* __restrict__ A,
    const __nv_bfloat16* __restrict__ Bh, const __nv_bfloat16* __restrict__ Bl,
    const float* __restrict__ bias, float* __restrict__ C,
    int M, int N, int K)
{
    extern __shared__ char smem[];
    const uint32_t sb32 = smem_u32(smem);

    const int tid = threadIdx.x;
    const int wid = tid >> 5, lane = tid & 31;
    const int warp_m = wid & 1;       // 2 x 32 rows
    const int warp_n = wid >> 1;      // 4 x 32 cols
    const int row0 = blockIdx.y * 64, col0 = blockIdx.x * 128;

    const int mat = lane >> 3, r8 = lane & 7;
    const uint32_t aoff = (uint32_t)((warp_m * 32 + (mat & 1) * 8 + r8) * APITCH + (mat >> 1) * 16);
    const uint32_t boff = (uint32_t)((warp_n * 32 + (mat >> 1) * 8 + r8) * APITCH + (mat & 1) * 16);

    float acc[2][4][4];
#pragma unroll
    for (int i = 0; i < 2; i++)
#pragma unroll
        for (int j = 0; j < 4; j++)
#pragma unroll
            for (int q = 0; q < 4; q++) acc[i][j][q] = 0.f;

    const int nk = K >> 5;
    float4 pa[2];

    auto ldg_A = [&](int kc) {
#pragma unroll
        for (int it = 0; it < 2; it++) {
            int i = tid + it * 256;
            int r = i >> 3, kq = i & 7;
            pa[it] = *(const float4*)(A + (size_t)(row0 + r) * K + kc + kq * 4);
        }
    };
    auto sts_A = [&](int bb) {
        char* dAh = smem + bb * BUF_BYTES;
        char* dAl = dAh + OFF_AL;
#pragma unroll
        for (int it = 0; it < 2; it++) {
            int i = tid + it * 256;
            int r = i >> 3, kq = i & 7;
            float4 v = pa[it];
            __nv_bfloat16 h0, h1, h2, h3;
            uint2 uh, ul;
            uh.x = pack_split_hi(v.x, v.y, h0, h1);
            uh.y = pack_split_hi(v.z, v.w, h2, h3);
            ul.x = pack_lo(v.x, v.y, h0, h1);
            ul.y = pack_lo(v.z, v.w, h2, h3);
            *(uint2*)(dAh + r * APITCH + kq * 8) = uh;
            *(uint2*)(dAl + r * APITCH + kq * 8) = ul;
        }
    };
    auto cpasync_B = [&](int kc, int bb) {
        uint32_t dBh = sb32 + bb * BUF_BYTES + OFF_BH;
        uint32_t dBl = sb32 + bb * BUF_BYTES + OFF_BL;
#pragma unroll
        for (int it = 0; it < 2; it++) {
            int i = tid + it * 256;
            int n = i >> 2, kq = i & 3;
            size_t goff = (size_t)(col0 + n) * K + kc + kq * 8;
            CP_ASYNC16(dBh + n * APITCH + kq * 16, Bh + goff);
            CP_ASYNC16(dBl + n * APITCH + kq * 16, Bl + goff);
        }
        CP_COMMIT();
    };

    ldg_A(0);
    cpasync_B(0, 0);
    sts_A(0);
    CP_WAIT0();
    __syncthreads();

    int buf = 0;
    for (int c = 0; c < nk; c++) {
        if (c + 1 < nk) {
            ldg_A((c + 1) << 5);
            cpasync_B((c + 1) << 5, buf ^ 1);
        }

        const uint32_t base = sb32 + buf * BUF_BYTES;
#pragma unroll
        for (int ks = 0; ks < 2; ks++) {
            const int kb = ks * 32;
            uint32_t ah[2][4], al[2][4];
            LDSM4(ah[0][0], ah[0][1], ah[0][2], ah[0][3], base + aoff + kb);
            LDSM4(ah[1][0], ah[1][1], ah[1][2], ah[1][3], base + aoff + kb + 16 * APITCH);
            LDSM4(al[0][0], al[0][1], al[0][2], al[0][3], base + OFF_AL + aoff + kb);
            LDSM4(al[1][0], al[1][1], al[1][2], al[1][3], base + OFF_AL + aoff + kb + 16 * APITCH);
#pragma unroll
            for (int p = 0; p < 2; p++) {
                uint32_t bq = base + OFF_BH + boff + kb + p * 16 * APITCH;
                uint32_t bhv[4], blv[4];
                LDSM4(bhv[0], bhv[1], bhv[2], bhv[3], bq);
                LDSM4(blv[0], blv[1], blv[2], blv[3], bq + B_TILE);
#pragma unroll
                for (int sub = 0; sub < 2; sub++) {
                    uint32_t bh2[2] = {bhv[2 * sub], bhv[2 * sub + 1]};
                    uint32_t bl2[2] = {blv[2 * sub], blv[2 * sub + 1]};
                    const int nt = 2 * p + sub;
#pragma unroll
                    for (int mt = 0; mt < 2; mt++) {
                        MMA_BF16(acc[mt][nt], ah[mt], bh2);
                        MMA_BF16(acc[mt][nt], ah[mt], bl2);
                        MMA_BF16(acc[mt][nt], al[mt], bh2);
                    }
                }
            }
        }

        if (c + 1 < nk) {
            sts_A(buf ^ 1);
            CP_WAIT0();
        }
        __syncthreads();
        buf ^= 1;
    }

#pragma unroll
    for (int mt = 0; mt < 2; mt++) {
        int r0 = row0 + warp_m * 32 + mt * 16 + (lane >> 2);
        float s0 = 1.f, s1 = 1.f;
        if (SCALE) { s0 = g_dinv[r0]; s1 = g_dinv[r0 + 8]; }
#pragma unroll
        for (int nt = 0; nt < 4; nt++) {
            int c = col0 + warp_n * 32 + nt * 8 + (lane & 3) * 2;
            float v0 = acc[mt][nt][0], v1 = acc[mt][nt][1];
            float v2 = acc[mt][nt][2], v3 = acc[mt][nt][3];
            if (BIAS) {
                float b0 = bias[c], b1 = bias[c + 1];
                v0 += b0; v1 += b1; v2 += b0; v3 += b1;
            }
            if (SCALE) { v0 *= s0; v1 *= s0; v2 *= s1; v3 *= s1; }
            if (RELU) {
                v0 = fmaxf(v0, 0.f); v1 = fmaxf(v1, 0.f);
                v2 = fmaxf(v2, 0.f); v3 = fmaxf(v3, 0.f);
            }
            *(float2*)(C + (size_t)r0 * N + c) = make_float2(v0, v1);
            *(float2*)(C + (size_t)(r0 + 8) * N + c) = make_float2(v2, v3);
        }
    }
}

// ---------------- vn mma GEMM: vn[b] = mw[b]^T (64x512) @ g[b] (512x256) ----------------
__global__ void __launch_bounds__(256) vn_mma_kernel(
    const float* __restrict__ mw, const float* __restrict__ gfeat, float* __restrict__ vn)
{
    __shared__ __align__(16) char sAh[64 * APITCH];
    __shared__ __align__(16) char sAl[64 * APITCH];
    __shared__ __align__(16) char sBh[128 * APITCH];
    __shared__ __align__(16) char sBl[128 * APITCH];

    const int b = blockIdx.y;
    const int col0 = blockIdx.x * 128;
    const float* mwb = mw + (size_t)b * NN * VV;
    const float* gb  = gfeat + (size_t)b * NN * HH;
    float* vnb = vn + (size_t)b * VV * HH;

    const int tid = threadIdx.x;
    const int wid = tid >> 5, lane = tid & 31;
    const int warp_m = wid & 1;
    const int warp_n = wid >> 1;
    const int lr = lane >> 2;
    const int lk4 = (lane & 3) * 4;

    float acc[2][4][4];
#pragma unroll
    for (int i = 0; i < 2; i++)
#pragma unroll
        for (int j = 0; j < 4; j++)
#pragma unroll
            for (int q = 0; q < 4; q++) acc[i][j][q] = 0.f;

    for (int kc = 0; kc < NN; kc += 32) {
#pragma unroll
        for (int it = 0; it < 4; it++) {
            int i = tid + it * 256;
            int v = i & 63, kp = i >> 6;
            float x0 = mwb[(size_t)(kc + 2 * kp) * VV + v];
            float x1 = mwb[(size_t)(kc + 2 * kp + 1) * VV + v];
            __nv_bfloat16 h0, h1;
            uint32_t uh = pack_split_hi(x0, x1, h0, h1);
            uint32_t ul = pack_lo(x0, x1, h0, h1);
            *(uint32_t*)(sAh + v * APITCH + kp * 4) = uh;
            *(uint32_t*)(sAl + v * APITCH + kp * 4) = ul;
        }
#pragma unroll
        for (int it = 0; it < 8; it++) {
            int i = tid + it * 256;
            int n = i & 127, kp = i >> 7;
            float x0 = gb[(size_t)(kc + 2 * kp) * HH + col0 + n];
            float x1 = gb[(size_t)(kc + 2 * kp + 1) * HH + col0 + n];
            __nv_bfloat16 h0, h1;
            uint32_t uh = pack_split_hi(x0, x1, h0, h1);
            uint32_t ul = pack_lo(x0, x1, h0, h1);
            *(uint32_t*)(sBh + n * APITCH + kp * 4) = uh;
            *(uint32_t*)(sBl + n * APITCH + kp * 4) = ul;
        }
        __syncthreads();

#pragma unroll
        for (int ks = 0; ks < 2; ks++) {
            const int kb = ks * 32;
            uint32_t ah[2][4], al[2][4];
#pragma unroll
            for (int mt = 0; mt < 2; mt++) {
                const char* base = sAh + (warp_m * 32 + mt * 16 + lr) * APITCH + kb + lk4;
                ah[mt][0] = *(const uint32_t*)base;
                ah[mt][1] = *(const uint32_t*)(base + 8 * APITCH);
                ah[mt][2] = *(const uint32_t*)(base + 16);
                ah[mt][3] = *(const uint32_t*)(base + 8 * APITCH + 16);
                const char* basel = sAl + (warp_m * 32 + mt * 16 + lr) * APITCH + kb + lk4;
                al[mt][0] = *(const uint32_t*)basel;
                al[mt][1] = *(const uint32_t*)(basel + 8 * APITCH);
                al[mt][2] = *(const uint32_t*)(basel + 16);
                al[mt][3] = *(const uint32_t*)(basel + 8 * APITCH + 16);
            }
#pragma unroll
            for (int nt = 0; nt < 4; nt++) {
                const char* bbase = sBh + (warp_n * 32 + nt * 8 + lr) * APITCH + kb + lk4;
                uint32_t bh[2], bl[2];
                bh[0] = *(const uint32_t*)bbase;
                bh[1] = *(const uint32_t*)(bbase + 16);
                const char* bbl = sBl + (warp_n * 32 + nt * 8 + lr) * APITCH + kb + lk4;
                bl[0] = *(const uint32_t*)bbl;
                bl[1] = *(const uint32_t*)(bbl + 16);
#pragma unroll
                for (int mt = 0; mt < 2; mt++) {
                    MMA_BF16(acc[mt][nt], ah[mt], bh);
                    MMA_BF16(acc[mt][nt], ah[mt], bl);
                    MMA_BF16(acc[mt][nt], al[mt], bh);
                }
            }
        }
        __syncthreads();
    }

#pragma unroll
    for (int mt = 0; mt < 2; mt++) {
        int r0 = warp_m * 32 + mt * 16 + lr;
#pragma unroll
        for (int nt = 0; nt < 4; nt++) {
            int c = col0 + warp_n * 32 + nt * 8 + (lane & 3) * 2;
            *(float2*)(vnb + (size_t)r0 * HH + c) = make_float2(acc[mt][nt][0], acc[mt][nt][1]);
            *(float2*)(vnb + (size_t)(r0 + 8) * HH + c) = make_float2(acc[mt][nt][2], acc[mt][nt][3]);
        }
    }
}

// ---------------- GCN gather (bucket CSR, prescaled hw, MLP=4) + scale + bias + relu ----------------
__global__ void gather_gcn_kernel(const float* __restrict__ bgcn) {
    int node = blockIdx.x * 4 + threadIdx.y;
    int t = threadIdx.x;              // 0..63
    const float4* hw4 = (const float4*)g_hw;    // prescaled by dinv[row]
    const int* csr = g_csr + node * BUCKET;
    int deg = g_cursor[node];
    float di = g_dinv[node];
    float4 acc = make_float4(0.f, 0.f, 0.f, 0.f);
    int e = 0;
    for (; e + 4 <= deg; e += 4) {
        int s0 = csr[e], s1 = csr[e + 1], s2 = csr[e + 2], s3 = csr[e + 3];
        float4 v0 = hw4[(size_t)s0 * 64 + t];
        float4 v1 = hw4[(size_t)s1 * 64 + t];
        float4 v2 = hw4[(size_t)s2 * 64 + t];
        float4 v3 = hw4[(size_t)s3 * 64 + t];
        acc.x += v0.x + v1.x + v2.x + v3.x;
        acc.y += v0.y + v1.y + v2.y + v3.y;
        acc.z += v0.z + v1.z + v2.z + v3.z;
        acc.w += v0.w + v1.w + v2.w + v3.w;
    }
    for (; e < deg; e++) {
        int s = csr[e];
        float4 v = hw4[(size_t)s * 64 + t];
        acc.x += v.x; acc.y += v.y; acc.z += v.z; acc.w += v.w;
    }
    float4 vs = hw4[(size_t)node * 64 + t];
    acc.x = (acc.x + vs.x) * di;
    acc.y = (acc.y + vs.y) * di;
    acc.z = (acc.z + vs.z) * di;
    acc.w = (acc.w + vs.w) * di;
    float4 bb = ((const float4*)bgcn)[t];
    acc.x = fmaxf(acc.x + bb.x, 0.f);
    acc.y = fmaxf(acc.y + bb.y, 0.f);
    acc.z = fmaxf(acc.z + bb.z, 0.f);
    acc.w = fmaxf(acc.w + bb.w, 0.f);
    ((float4*)g_h)[(size_t)node * 64 + t] = acc;
}

// ---------------- proto: partial column sums (full-chip) then mean+norm ----------------
__global__ void proto_partial_kernel() {
    // grid (8, 64): blockIdx.y = graph, blockIdx.x = 64-node chunk
    int b = blockIdx.y, chunk = blockIdx.x;
    int h = threadIdx.x;   // 256
    const float* tb = g_t + (size_t)b * NN * HH + (size_t)chunk * 64 * HH;
    float s = 0.f;
#pragma unroll 8
    for (int n = 0; n < 64; n++) s += tb[(size_t)n * HH + h];
    atomicAdd(&g_proto[b * HH + h], s);
}

__global__ void pn_kernel() {
    int b = blockIdx.x;
    int h = threadIdx.x;   // 256
    float m = g_proto[b * HH + h] * (1.0f / NN);
    g_proto[b * HH + h] = m;
    __shared__ float red[256];
    red[h] = m * m;
    __syncthreads();
    for (int off = 128; off > 0; off >>= 1) {
        if (h < off) red[h] += red[h + off];
        __syncthreads();
    }
    if (h == 0) g_pn[b] = fmaxf(sqrtf(red[0]), 1e-8f);
}

// ---------------- fused attention + mw (warp per node) ----------------
__global__ void att_mw_kernel(const float* __restrict__ ew) {
    int w = (blockIdx.x * blockDim.x + threadIdx.x) >> 5;
    int lane = threadIdx.x & 31;
    if (w >= TOTAL_NODES) return;
    int b = w >> 9;
    const float* tr = g_t + (size_t)w * HH;
    const float* pr = g_proto + b * HH;
    float dot = 0.f, nrm = 0.f;
    for (int j = lane; j < HH; j += 32) {
        float v = tr[j];
        dot += v * pr[j];
        nrm += v * v;
    }
#pragma unroll
    for (int off = 16; off; off >>= 1) {
        dot += __shfl_xor_sync(0xffffffffu, dot, off);
        nrm += __shfl_xor_sync(0xffffffffu, nrm, off);
    }
    float tn = fmaxf(sqrtf(nrm), 1e-8f);
    float sim = dot / (tn * g_pn[b]);
    float a = 0.5f * (1.0f + sim);

    const float* e = ew + (size_t)w * VV;
    float v0 = e[lane] * a;
    float v1 = e[lane + 32] * a;
    float rs = v0 + v1;
#pragma unroll
    for (int off = 16; off; off >>= 1) rs += __shfl_xor_sync(0xffffffffu, rs, off);
    float sc = (rs == 0.0f) ? 1.0f : (1.0f / rs);
    float* m = g_mw + (size_t)w * VV;
    m[lane]      = v0 * sc;
    m[lane + 32] = v1 * sc;
}

// ---------------- fused readout ----------------
__global__ void __launch_bounds__(256) readout_kernel(
    const float* __restrict__ mW1, const float* __restrict__ mb1,
    const float* __restrict__ mW2, const float* __restrict__ mb2,
    float* __restrict__ out)
{
    __shared__ float sgf[HH];
    __shared__ float sm1[HH];
    const int b = blockIdx.x, h = threadIdx.x;

    const float* v = g_vn3 + (size_t)b * VV * HH;
    float s = 0.f;
#pragma unroll 8
    for (int i = 0; i < VV; i++) s += v[i * HH + h];
    sgf[h] = s * (1.0f / VV);
    __syncthreads();

    float acc = mb1[h];
    for (int k = 0; k < HH; k++) acc += sgf[k] * mW1[(size_t)k * HH + h];
    sm1[h] = fmaxf(acc, 0.f);
    __syncthreads();

    if (h < OUTD) {
        float o = mb2[h];
        for (int k = 0; k < HH; k++) o += sm1[k] * mW2[(size_t)k * OUTD + h];
        out[b * OUTD + h] = o;
    }
}

// ---------------- launch ----------------
extern "C" void kernel_launch(void* const* d_in, const int* in_sizes, int n_in,
                              void* d_out, int out_size)
{
    const float* x     = (const float*)d_in[0];
    const int*   esrc  = (const int*)  d_in[1];
    const int*   edst  = (const int*)  d_in[2];
    const float* W_emb = (const float*)d_in[3];
    const float* b_emb = (const float*)d_in[4];
    const float* W_gcn = (const float*)d_in[5];
    const float* b_gcn = (const float*)d_in[6];
    const float* aW1   = (const float*)d_in[7];
    const float* ab1   = (const float*)d_in[8];
    const float* aW2   = (const float*)d_in[9];
    const float* ab2   = (const float*)d_in[10];
    const float* vW1   = (const float*)d_in[11];
    const float* vb1   = (const float*)d_in[12];
    const float* vW2   = (const float*)d_in[13];
    const float* vb2   = (const float*)d_in[14];
    const float* mW1   = (const float*)d_in[15];
    const float* mb1   = (const float*)d_in[16];
    const float* mW2   = (const float*)d_in[17];
    const float* mb2   = (const float*)d_in[18];
    const float* ew    = (const float*)d_in[19];
    float* out = (float*)d_out;

    float *h, *hw, *t1, *t, *mw, *vn, *vn2, *vn3;
    __nv_bfloat16 *wh, *wl;
    cudaGetSymbolAddress((void**)&h,   g_h);
    cudaGetSymbolAddress((void**)&hw,  g_hw);
    cudaGetSymbolAddress((void**)&t1,  g_t1);
    cudaGetSymbolAddress((void**)&t,   g_t);
    cudaGetSymbolAddress((void**)&mw,  g_mw);
    cudaGetSymbolAddress((void**)&vn,  g_vn);
    cudaGetSymbolAddress((void**)&vn2, g_vn2);
    cudaGetSymbolAddress((void**)&vn3, g_vn3);
    cudaGetSymbolAddress((void**)&wh,  g_wh);
    cudaGetSymbolAddress((void**)&wl,  g_wl);

    static bool attr_done = false;
    if (!attr_done) {
        cudaFuncSetAttribute(gemm_mma_kernel<false, true,  false>, cudaFuncAttributeMaxDynamicSharedMemorySize, GEMM_SMEM);
        cudaFuncSetAttribute(gemm_mma_kernel<false, false, true>,  cudaFuncAttributeMaxDynamicSharedMemorySize, GEMM_SMEM);
        cudaFuncSetAttribute(gemm_mma_kernel<true,  true,  false>, cudaFuncAttributeMaxDynamicSharedMemorySize, GEMM_SMEM);
        attr_done = true;
    }

    const int WS = 256 * 256;   // weight slot stride

    // launches 1-3
    split_all_kernel<<<dim3(256, 6), 256>>>(W_emb, W_gcn, aW1, aW2, vW1, vW2);
    zero_cursor_kernel<<<TOTAL_NODES / 256, 256>>>();
    fill_kernel<<<EE / 256, 256>>>(esrc, edst);

    // launch 4: first big GEMM (profiler lands here)
    gemm_mma_kernel<false, true, false><<<dim3(HH / 128, TOTAL_NODES / 64), 256, GEMM_SMEM>>>(
        x, wh + 0 * WS, wl + 0 * WS, b_emb, h, TOTAL_NODES, HH, INF_);

    dinv_kernel<<<TOTAL_NODES / 256, 256>>>();

    // hw = (h @ W_gcn) * dinv[row]   (prescaled for gather)
    gemm_mma_kernel<false, false, true><<<dim3(HH / 128, TOTAL_NODES / 64), 256, GEMM_SMEM>>>(
        h, wh + 1 * WS, wl + 1 * WS, nullptr, hw, TOTAL_NODES, HH, HH);
    // g = relu(dinv_d * (sum + self) + b_gcn)  (overwrites g_h)
    gather_gcn_kernel<<<TOTAL_NODES / 4, dim3(64, 4)>>>(b_gcn);

    // t = relu(g@aW1+ab1)@aW2+ab2
    gemm_mma_kernel<true, true, false><<<dim3(HH / 128, TOTAL_NODES / 64), 256, GEMM_SMEM>>>(
        h, wh + 2 * WS, wl + 2 * WS, ab1, t1, TOTAL_NODES, HH, HH);
    gemm_mma_kernel<false, true, false><<<dim3(HH / 128, TOTAL_NODES / 64), 256, GEMM_SMEM>>>(
        t1, wh + 3 * WS, wl + 3 * WS, ab2, t, TOTAL_NODES, HH, HH);

    // attention: full-chip proto partial sums, then mean+norm, then att+mw
    proto_partial_kernel<<<dim3(8, BG), 256>>>();
    pn_kernel<<<BG, 256>>>();
    att_mw_kernel<<<TOTAL_NODES * 32 / 256, 256>>>(ew);

    // vn = mw^T @ g (per graph) via mma, then vn MLP
    vn_mma_kernel<<<dim3(2, BG), 256>>>(mw, h, vn);
    gemm_mma_kernel<true, true, false><<<dim3(HH / 128, BG * VV / 64), 256, GEMM_SMEM>>>(
        vn, wh + 4 * WS, wl + 4 * WS, vb1, vn2, BG * VV, HH, HH);
    gemm_mma_kernel<false, true, false><<<dim3(HH / 128, BG * VV / 64), 256, GEMM_SMEM>>>(
        vn2, wh + 5 * WS, wl + 5 * WS, vb2, vn3, BG * VV, HH, HH);

    // fused readout (gf + m1 GEMM + out)
    readout_kernel<<<BG, 256>>>(mW1, mb1, mW2, mb2, out);
}

// round 17
// speedup vs baseline: 1.0654x; 1.0179x over previous
#include <cuda_runtime.h>
#include <cuda_bf16.h>
#include <math.h>
#include <cstdint>

// Problem constants (fixed shapes from the reference)
#define TOTAL_NODES 32768
#define BG   64
#define NN   512
#define VV   64
#define EE   1048576
#define INF_ 128
#define HH   256
#define OUTD 10
#define BUCKET 128   // fixed CSR bucket per node (avg deg 32, P(>128) ~ 0)

// ---------------- scratch (static device globals; no allocation) ----------------
__device__ float g_h  [TOTAL_NODES * HH];   // g (post-GCN)
__device__ float g_hw [TOTAL_NODES * HH];   // dinv-prescaled hw
__device__ float g_t1 [TOTAL_NODES * HH];
__device__ float g_t  [TOTAL_NODES * HH];
__device__ float g_proto[BG * HH];          // accumulates sums, then mean in-place
__device__ float g_pn [BG];
__device__ float g_mw [BG * NN * VV];
__device__ float g_vn [BG * VV * HH];
__device__ float g_vn2[BG * VV * HH];
__device__ float g_vn3[BG * VV * HH];
__device__ int   g_cursor[TOTAL_NODES];
__device__ int   g_csr   [TOTAL_NODES * BUCKET];   // 16 MB fixed-stride buckets
// pre-split transposed weights: 6 slots of [N,K] bf16 (slot stride 256*256)
__device__ __nv_bfloat16 g_wh[6 * 256 * 256];
__device__ __nv_bfloat16 g_wl[6 * 256 * 256];

// ---------------- bucket CSR build (no scan) + proto zero ----------------
__global__ void zero_cursor_kernel() {
    int i = blockIdx.x * blockDim.x + threadIdx.x;
    if (i < TOTAL_NODES) g_cursor[i] = 0;
    if (i < BG * HH) g_proto[i] = 0.f;
}

__global__ void fill_kernel(const int* __restrict__ src, const int* __restrict__ dst) {
    int e = blockIdx.x * blockDim.x + threadIdx.x;
    if (e < EE) {
        int d = dst[e];
        int p = atomicAdd(&g_cursor[d], 1);
        g_csr[d * BUCKET + p] = src[e];
    }
}

// ---------------- fused weight split+transpose: all 6 weights in one launch ----------------
__global__ void split_all_kernel(const float* __restrict__ w0, const float* __restrict__ w1,
                                 const float* __restrict__ w2, const float* __restrict__ w3,
                                 const float* __restrict__ w4, const float* __restrict__ w5) {
    int slot = blockIdx.y;
    const float* W;
    switch (slot) {
        case 0: W = w0; break; case 1: W = w1; break; case 2: W = w2; break;
        case 3: W = w3; break; case 4: W = w4; break; default: W = w5; break;
    }
    int K = (slot == 0) ? INF_ : HH;
    int idx = blockIdx.x * 256 + threadIdx.x;
    if (idx >= K * HH) return;
    int k = idx / HH, n = idx % HH;
    float v = W[idx];
    __nv_bfloat16 hb = __float2bfloat16_rn(v);
    float r = v - __bfloat162float(hb);
    size_t o = (size_t)slot * (256 * 256) + (size_t)n * K + k;
    g_wh[o] = hb;
    g_wl[o] = __float2bfloat16_rn(r);
}

// ---------------- mma.sync bf16-split GEMM ----------------
// 64(M) x 128(N) CTA tile, BK=32, 8 warps (2x4), warp tile 32x32.
// Double-buffered, cp.async for B, ldmatrix fragments, 3 CTAs/SM.
// SCALE: multiply output row r by rsqrt(1+cursor[r]) (GCN prescale; dinv computed inline).
// PROTO: atomically accumulate per-column sums of the output tile into g_proto.
#define MMA_BF16(d, a, b) \
    asm volatile("mma.sync.aligned.m16n8k16.row.col.f32.bf16.bf16.f32 " \
        "{%0,%1,%2,%3}, {%4,%5,%6,%7}, {%8,%9}, {%0,%1,%2,%3};" \
        : "+f"((d)[0]), "+f"((d)[1]), "+f"((d)[2]), "+f"((d)[3]) \
        : "r"((a)[0]), "r"((a)[1]), "r"((a)[2]), "r"((a)[3]), "r"((b)[0]), "r"((b)[1]))

#define LDSM4(r0, r1, r2, r3, addr) \
    asm volatile("ldmatrix.sync.aligned.m8n8.x4.shared.b16 {%0,%1,%2,%3}, [%4];" \
        : "=r"(r0), "=r"(r1), "=r"(r2), "=r"(r3) : "r"(addr))

#define APITCH 80                     // bytes per 32-bf16 row (64B data + 16B pad)
#define A_TILE (64 * APITCH)          // 5120
#define B_TILE (128 * APITCH)         // 10240
#define BUF_BYTES (2 * A_TILE + 2 * B_TILE)   // 30720: Ah, Al, Bh, Bl
#define OFF_AL  A_TILE
#define OFF_BH  (2 * A_TILE)
#define OFF_BL  (2 * A_TILE + B_TILE)
#define GEMM_SMEM (2 * BUF_BYTES)     // 61440

__device__ __forceinline__ uint32_t smem_u32(const void* p) {
    uint32_t a;
    asm("{ .reg .u64 t; cvta.to.shared.u64 t, %1; cvt.u32.u64 %0, t; }" : "=r"(a) : "l"(p));
    return a;
}
#define CP_ASYNC16(saddr, gptr) \
    asm volatile("cp.async.cg.shared.global [%0], [%1], 16;" :: "r"(saddr), "l"(gptr))
#define CP_COMMIT() asm volatile("cp.async.commit_group;" ::: "memory")
#define CP_WAIT0()  asm volatile("cp.async.wait_group 0;" ::: "memory")

__device__ __forceinline__ uint32_t pack_split_hi(float a, float b,
                                                  __nv_bfloat16& ha, __nv_bfloat16& hb) {
    ha = __float2bfloat16_rn(a);
    hb = __float2bfloat16_rn(b);
    return (uint32_t)__bfloat16_as_ushort(ha) | ((uint32_t)__bfloat16_as_ushort(hb) << 16);
}
__device__ __forceinline__ uint32_t pack_lo(float a, float b, __nv_bfloat16 ha, __nv_bfloat16 hb) {
    __nv_bfloat16 la = __float2bfloat16_rn(a - __bfloat162float(ha));
    __nv_bfloat16 lb = __float2bfloat16_rn(b - __bfloat162float(hb));
    return (uint32_t)__bfloat16_as_ushort(la) | ((uint32_t)__bfloat16_as_ushort(lb) << 16);
}

template<bool RELU, bool BIAS, bool SCALE, bool PROTO>
__global__ void __launch_bounds__(256, 3) gemm_mma_kernel(
    const float* __restrict__ A,
    const __nv_bfloat16* __restrict__ Bh, const __nv_bfloat16* __restrict__ Bl,
    const float* __restrict__ bias, float* __restrict__ C,
    int M, int N, int K)
{
    extern __shared__ char smem[];
    const uint32_t sb32 = smem_u32(smem);

    const int tid = threadIdx.x;
    const int wid = tid >> 5, lane = tid & 31;
    const int warp_m = wid & 1;       // 2 x 32 rows
    const int warp_n = wid >> 1;      // 4 x 32 cols
    const int row0 = blockIdx.y * 64, col0 = blockIdx.x * 128;

    const int mat = lane >> 3, r8 = lane & 7;
    const uint32_t aoff = (uint32_t)((warp_m * 32 + (mat & 1) * 8 + r8) * APITCH + (mat >> 1) * 16);
    const uint32_t boff = (uint32_t)((warp_n * 32 + (mat >> 1) * 8 + r8) * APITCH + (mat & 1) * 16);

    float acc[2][4][4];
#pragma unroll
    for (int i = 0; i < 2; i++)
#pragma unroll
        for (int j = 0; j < 4; j++)
#pragma unroll
            for (int q = 0; q < 4; q++) acc[i][j][q] = 0.f;

    const int nk = K >> 5;
    float4 pa[2];

    auto ldg_A = [&](int kc) {
#pragma unroll
        for (int it = 0; it < 2; it++) {
            int i = tid + it * 256;
            int r = i >> 3, kq = i & 7;
            pa[it] = *(const float4*)(A + (size_t)(row0 + r) * K + kc + kq * 4);
        }
    };
    auto sts_A = [&](int bb) {
        char* dAh = smem + bb * BUF_BYTES;
        char* dAl = dAh + OFF_AL;
#pragma unroll
        for (int it = 0; it < 2; it++) {
            int i = tid + it * 256;
            int r = i >> 3, kq = i & 7;
            float4 v = pa[it];
            __nv_bfloat16 h0, h1, h2, h3;
            uint2 uh, ul;
            uh.x = pack_split_hi(v.x, v.y, h0, h1);
            uh.y = pack_split_hi(v.z, v.w, h2, h3);
            ul.x = pack_lo(v.x, v.y, h0, h1);
            ul.y = pack_lo(v.z, v.w, h2, h3);
            *(uint2*)(dAh + r * APITCH + kq * 8) = uh;
            *(uint2*)(dAl + r * APITCH + kq * 8) = ul;
        }
    };
    auto cpasync_B = [&](int kc, int bb) {
        uint32_t dBh = sb32 + bb * BUF_BYTES + OFF_BH;
        uint32_t dBl = sb32 + bb * BUF_BYTES + OFF_BL;
#pragma unroll
        for (int it = 0; it < 2; it++) {
            int i = tid + it * 256;
            int n = i >> 2, kq = i & 3;
            size_t goff = (size_t)(col0 + n) * K + kc + kq * 8;
            CP_ASYNC16(dBh + n * APITCH + kq * 16, Bh + goff);
            CP_ASYNC16(dBl + n * APITCH + kq * 16, Bl + goff);
        }
        CP_COMMIT();
    };

    ldg_A(0);
    cpasync_B(0, 0);
    sts_A(0);
    CP_WAIT0();
    __syncthreads();

    int buf = 0;
    for (int c = 0; c < nk; c++) {
        if (c + 1 < nk) {
            ldg_A((c + 1) << 5);
            cpasync_B((c + 1) << 5, buf ^ 1);
        }

        const uint32_t base = sb32 + buf * BUF_BYTES;
#pragma unroll
        for (int ks = 0; ks < 2; ks++) {
            const int kb = ks * 32;
            uint32_t ah[2][4], al[2][4];
            LDSM4(ah[0][0], ah[0][1], ah[0][2], ah[0][3], base + aoff + kb);
            LDSM4(ah[1][0], ah[1][1], ah[1][2], ah[1][3], base + aoff + kb + 16 * APITCH);
            LDSM4(al[0][0], al[0][1], al[0][2], al[0][3], base + OFF_AL + aoff + kb);
            LDSM4(al[1][0], al[1][1], al[1][2], al[1][3], base + OFF_AL + aoff + kb + 16 * APITCH);
#pragma unroll
            for (int p = 0; p < 2; p++) {
                uint32_t bq = base + OFF_BH + boff + kb + p * 16 * APITCH;
                uint32_t bhv[4], blv[4];
                LDSM4(bhv[0], bhv[1], bhv[2], bhv[3], bq);
                LDSM4(blv[0], blv[1], blv[2], blv[3], bq + B_TILE);
#pragma unroll
                for (int sub = 0; sub < 2; sub++) {
                    uint32_t bh2[2] = {bhv[2 * sub], bhv[2 * sub + 1]};
                    uint32_t bl2[2] = {blv[2 * sub], blv[2 * sub + 1]};
                    const int nt = 2 * p + sub;
#pragma unroll
                    for (int mt = 0; mt < 2; mt++) {
                        MMA_BF16(acc[mt][nt], ah[mt], bh2);
                        MMA_BF16(acc[mt][nt], ah[mt], bl2);
                        MMA_BF16(acc[mt][nt], al[mt], bh2);
                    }
                }
            }
        }

        if (c + 1 < nk) {
            sts_A(buf ^ 1);
            CP_WAIT0();
        }
        __syncthreads();
        buf ^= 1;
    }

    // epilogue
    float ps[4][2];   // PROTO per-column partial sums
#pragma unroll
    for (int nt = 0; nt < 4; nt++) { ps[nt][0] = 0.f; ps[nt][1] = 0.f; }

#pragma unroll
    for (int mt = 0; mt < 2; mt++) {
        int r0 = row0 + warp_m * 32 + mt * 16 + (lane >> 2);
        float s0 = 1.f, s1 = 1.f;
        if (SCALE) {
            s0 = rsqrtf(1.0f + (float)g_cursor[r0]);
            s1 = rsqrtf(1.0f + (float)g_cursor[r0 + 8]);
        }
#pragma unroll
        for (int nt = 0; nt < 4; nt++) {
            int c = col0 + warp_n * 32 + nt * 8 + (lane & 3) * 2;
            float v0 = acc[mt][nt][0], v1 = acc[mt][nt][1];
            float v2 = acc[mt][nt][2], v3 = acc[mt][nt][3];
            if (BIAS) {
                float b0 = bias[c], b1 = bias[c + 1];
                v0 += b0; v1 += b1; v2 += b0; v3 += b1;
            }
            if (SCALE) { v0 *= s0; v1 *= s0; v2 *= s1; v3 *= s1; }
            if (RELU) {
                v0 = fmaxf(v0, 0.f); v1 = fmaxf(v1, 0.f);
                v2 = fmaxf(v2, 0.f); v3 = fmaxf(v3, 0.f);
            }
            if (PROTO) { ps[nt][0] += v0 + v2; ps[nt][1] += v1 + v3; }
            *(float2*)(C + (size_t)r0 * N + c) = make_float2(v0, v1);
            *(float2*)(C + (size_t)(r0 + 8) * N + c) = make_float2(v2, v3);
        }
    }

    if (PROTO) {
        const int b = row0 >> 9;   // 64-row tile lies within one 512-node graph
#pragma unroll
        for (int nt = 0; nt < 4; nt++) {
            float s0 = ps[nt][0], s1 = ps[nt][1];
            s0 += __shfl_down_sync(0xffffffffu, s0, 16);
            s0 += __shfl_down_sync(0xffffffffu, s0, 8);
            s0 += __shfl_down_sync(0xffffffffu, s0, 4);
            s1 += __shfl_down_sync(0xffffffffu, s1, 16);
            s1 += __shfl_down_sync(0xffffffffu, s1, 8);
            s1 += __shfl_down_sync(0xffffffffu, s1, 4);
            if ((lane >> 2) == 0) {
                int c = col0 + warp_n * 32 + nt * 8 + (lane & 3) * 2;
                atomicAdd(&g_proto[b * HH + c], s0);
                atomicAdd(&g_proto[b * HH + c + 1], s1);
            }
        }
    }
}

// ---------------- vn mma GEMM: vn[b] = mw[b]^T (64x512) @ g[b] (512x256) ----------------
__global__ void __launch_bounds__(256) vn_mma_kernel(
    const float* __restrict__ mw, const float* __restrict__ gfeat, float* __restrict__ vn)
{
    __shared__ __align__(16) char sAh[64 * APITCH];
    __shared__ __align__(16) char sAl[64 * APITCH];
    __shared__ __align__(16) char sBh[128 * APITCH];
    __shared__ __align__(16) char sBl[128 * APITCH];

    const int b = blockIdx.y;
    const int col0 = blockIdx.x * 128;
    const float* mwb = mw + (size_t)b * NN * VV;
    const float* gb  = gfeat + (size_t)b * NN * HH;
    float* vnb = vn + (size_t)b * VV * HH;

    const int tid = threadIdx.x;
    const int wid = tid >> 5, lane = tid & 31;
    const int warp_m = wid & 1;
    const int warp_n = wid >> 1;
    const int lr = lane >> 2;
    const int lk4 = (lane & 3) * 4;

    float acc[2][4][4];
#pragma unroll
    for (int i = 0; i < 2; i++)
#pragma unroll
        for (int j = 0; j < 4; j++)
#pragma unroll
            for (int q = 0; q < 4; q++) acc[i][j][q] = 0.f;

    for (int kc = 0; kc < NN; kc += 32) {
#pragma unroll
        for (int it = 0; it < 4; it++) {
            int i = tid + it * 256;
            int v = i & 63, kp = i >> 6;
            float x0 = mwb[(size_t)(kc + 2 * kp) * VV + v];
            float x1 = mwb[(size_t)(kc + 2 * kp + 1) * VV + v];
            __nv_bfloat16 h0, h1;
            uint32_t uh = pack_split_hi(x0, x1, h0, h1);
            uint32_t ul = pack_lo(x0, x1, h0, h1);
            *(uint32_t*)(sAh + v * APITCH + kp * 4) = uh;
            *(uint32_t*)(sAl + v * APITCH + kp * 4) = ul;
        }
#pragma unroll
        for (int it = 0; it < 8; it++) {
            int i = tid + it * 256;
            int n = i & 127, kp = i >> 7;
            float x0 = gb[(size_t)(kc + 2 * kp) * HH + col0 + n];
            float x1 = gb[(size_t)(kc + 2 * kp + 1) * HH + col0 + n];
            __nv_bfloat16 h0, h1;
            uint32_t uh = pack_split_hi(x0, x1, h0, h1);
            uint32_t ul = pack_lo(x0, x1, h0, h1);
            *(uint32_t*)(sBh + n * APITCH + kp * 4) = uh;
            *(uint32_t*)(sBl + n * APITCH + kp * 4) = ul;
        }
        __syncthreads();

#pragma unroll
        for (int ks = 0; ks < 2; ks++) {
            const int kb = ks * 32;
            uint32_t ah[2][4], al[2][4];
#pragma unroll
            for (int mt = 0; mt < 2; mt++) {
                const char* base = sAh + (warp_m * 32 + mt * 16 + lr) * APITCH + kb + lk4;
                ah[mt][0] = *(const uint32_t*)base;
                ah[mt][1] = *(const uint32_t*)(base + 8 * APITCH);
                ah[mt][2] = *(const uint32_t*)(base + 16);
                ah[mt][3] = *(const uint32_t*)(base + 8 * APITCH + 16);
                const char* basel = sAl + (warp_m * 32 + mt * 16 + lr) * APITCH + kb + lk4;
                al[mt][0] = *(const uint32_t*)basel;
                al[mt][1] = *(const uint32_t*)(basel + 8 * APITCH);
                al[mt][2] = *(const uint32_t*)(basel + 16);
                al[mt][3] = *(const uint32_t*)(basel + 8 * APITCH + 16);
            }
#pragma unroll
            for (int nt = 0; nt < 4; nt++) {
                const char* bbase = sBh + (warp_n * 32 + nt * 8 + lr) * APITCH + kb + lk4;
                uint32_t bh[2], bl[2];
                bh[0] = *(const uint32_t*)bbase;
                bh[1] = *(const uint32_t*)(bbase + 16);
                const char* bbl = sBl + (warp_n * 32 + nt * 8 + lr) * APITCH + kb + lk4;
                bl[0] = *(const uint32_t*)bbl;
                bl[1] = *(const uint32_t*)(bbl + 16);
#pragma unroll
                for (int mt = 0; mt < 2; mt++) {
                    MMA_BF16(acc[mt][nt], ah[mt], bh);
                    MMA_BF16(acc[mt][nt], ah[mt], bl);
                    MMA_BF16(acc[mt][nt], al[mt], bh);
                }
            }
        }
        __syncthreads();
    }

#pragma unroll
    for (int mt = 0; mt < 2; mt++) {
        int r0 = warp_m * 32 + mt * 16 + lr;
#pragma unroll
        for (int nt = 0; nt < 4; nt++) {
            int c = col0 + warp_n * 32 + nt * 8 + (lane & 3) * 2;
            *(float2*)(vnb + (size_t)r0 * HH + c) = make_float2(acc[mt][nt][0], acc[mt][nt][1]);
            *(float2*)(vnb + (size_t)(r0 + 8) * HH + c) = make_float2(acc[mt][nt][2], acc[mt][nt][3]);
        }
    }
}

// ---------------- GCN gather (bucket CSR, prescaled hw, MLP=4) + scale + bias + relu ----------------
__global__ void gather_gcn_kernel(const float* __restrict__ bgcn) {
    int node = blockIdx.x * 4 + threadIdx.y;
    int t = threadIdx.x;              // 0..63
    const float4* hw4 = (const float4*)g_hw;    // prescaled by dinv[row]
    const int* csr = g_csr + node * BUCKET;
    int deg = g_cursor[node];
    float di = rsqrtf(1.0f + (float)deg);
    float4 acc = make_float4(0.f, 0.f, 0.f, 0.f);
    int e = 0;
    for (; e + 4 <= deg; e += 4) {
        int s0 = csr[e], s1 = csr[e + 1], s2 = csr[e + 2], s3 = csr[e + 3];
        float4 v0 = hw4[(size_t)s0 * 64 + t];
        float4 v1 = hw4[(size_t)s1 * 64 + t];
        float4 v2 = hw4[(size_t)s2 * 64 + t];
        float4 v3 = hw4[(size_t)s3 * 64 + t];
        acc.x += v0.x + v1.x + v2.x + v3.x;
        acc.y += v0.y + v1.y + v2.y + v3.y;
        acc.z += v0.z + v1.z + v2.z + v3.z;
        acc.w += v0.w + v1.w + v2.w + v3.w;
    }
    for (; e < deg; e++) {
        int s = csr[e];
        float4 v = hw4[(size_t)s * 64 + t];
        acc.x += v.x; acc.y += v.y; acc.z += v.z; acc.w += v.w;
    }
    float4 vs = hw4[(size_t)node * 64 + t];
    acc.x = (acc.x + vs.x) * di;
    acc.y = (acc.y + vs.y) * di;
    acc.z = (acc.z + vs.z) * di;
    acc.w = (acc.w + vs.w) * di;
    float4 bb = ((const float4*)bgcn)[t];
    acc.x = fmaxf(acc.x + bb.x, 0.f);
    acc.y = fmaxf(acc.y + bb.y, 0.f);
    acc.z = fmaxf(acc.z + bb.z, 0.f);
    acc.w = fmaxf(acc.w + bb.w, 0.f);
    ((float4*)g_h)[(size_t)node * 64 + t] = acc;
}

// ---------------- pn: proto sums -> mean in place + ||proto|| ----------------
__global__ void pn_kernel() {
    int b = blockIdx.x;
    int h = threadIdx.x;   // 256
    float m = g_proto[b * HH + h] * (1.0f / NN);
    g_proto[b * HH + h] = m;
    __shared__ float red[256];
    red[h] = m * m;
    __syncthreads();
    for (int off = 128; off > 0; off >>= 1) {
        if (h < off) red[h] += red[h + off];
        __syncthreads();
    }
    if (h == 0) g_pn[b] = fmaxf(sqrtf(red[0]), 1e-8f);
}

// ---------------- fused attention + mw (warp per node) ----------------
__global__ void att_mw_kernel(const float* __restrict__ ew) {
    int w = (blockIdx.x * blockDim.x + threadIdx.x) >> 5;
    int lane = threadIdx.x & 31;
    if (w >= TOTAL_NODES) return;
    int b = w >> 9;
    const float* tr = g_t + (size_t)w * HH;
    const float* pr = g_proto + b * HH;
    float dot = 0.f, nrm = 0.f;
    for (int j = lane; j < HH; j += 32) {
        float v = tr[j];
        dot += v * pr[j];
        nrm += v * v;
    }
#pragma unroll
    for (int off = 16; off; off >>= 1) {
        dot += __shfl_xor_sync(0xffffffffu, dot, off);
        nrm += __shfl_xor_sync(0xffffffffu, nrm, off);
    }
    float tn = fmaxf(sqrtf(nrm), 1e-8f);
    float sim = dot / (tn * g_pn[b]);
    float a = 0.5f * (1.0f + sim);

    const float* e = ew + (size_t)w * VV;
    float v0 = e[lane] * a;
    float v1 = e[lane + 32] * a;
    float rs = v0 + v1;
#pragma unroll
    for (int off = 16; off; off >>= 1) rs += __shfl_xor_sync(0xffffffffu, rs, off);
    float sc = (rs == 0.0f) ? 1.0f : (1.0f / rs);
    float* m = g_mw + (size_t)w * VV;
    m[lane]      = v0 * sc;
    m[lane + 32] = v1 * sc;
}

// ---------------- fused readout ----------------
__global__ void __launch_bounds__(256) readout_kernel(
    const float* __restrict__ mW1, const float* __restrict__ mb1,
    const float* __restrict__ mW2, const float* __restrict__ mb2,
    float* __restrict__ out)
{
    __shared__ float sgf[HH];
    __shared__ float sm1[HH];
    const int b = blockIdx.x, h = threadIdx.x;

    const float* v = g_vn3 + (size_t)b * VV * HH;
    float s = 0.f;
#pragma unroll 8
    for (int i = 0; i < VV; i++) s += v[i * HH + h];
    sgf[h] = s * (1.0f / VV);
    __syncthreads();

    float acc = mb1[h];
    for (int k = 0; k < HH; k++) acc += sgf[k] * mW1[(size_t)k * HH + h];
    sm1[h] = fmaxf(acc, 0.f);
    __syncthreads();

    if (h < OUTD) {
        float o = mb2[h];
        for (int k = 0; k < HH; k++) o += sm1[k] * mW2[(size_t)k * OUTD + h];
        out[b * OUTD + h] = o;
    }
}

// ---------------- launch ----------------
extern "C" void kernel_launch(void* const* d_in, const int* in_sizes, int n_in,
                              void* d_out, int out_size)
{
    const float* x     = (const float*)d_in[0];
    const int*   esrc  = (const int*)  d_in[1];
    const int*   edst  = (const int*)  d_in[2];
    const float* W_emb = (const float*)d_in[3];
    const float* b_emb = (const float*)d_in[4];
    const float* W_gcn = (const float*)d_in[5];
    const float* b_gcn = (const float*)d_in[6];
    const float* aW1   = (const float*)d_in[7];
    const float* ab1   = (const float*)d_in[8];
    const float* aW2   = (const float*)d_in[9];
    const float* ab2   = (const float*)d_in[10];
    const float* vW1   = (const float*)d_in[11];
    const float* vb1   = (const float*)d_in[12];
    const float* vW2   = (const float*)d_in[13];
    const float* vb2   = (const float*)d_in[14];
    const float* mW1   = (const float*)d_in[15];
    const float* mb1   = (const float*)d_in[16];
    const float* mW2   = (const float*)d_in[17];
    const float* mb2   = (const float*)d_in[18];
    const float* ew    = (const float*)d_in[19];
    float* out = (float*)d_out;

    float *h, *hw, *t1, *t, *mw, *vn, *vn2, *vn3;
    __nv_bfloat16 *wh, *wl;
    cudaGetSymbolAddress((void**)&h,   g_h);
    cudaGetSymbolAddress((void**)&hw,  g_hw);
    cudaGetSymbolAddress((void**)&t1,  g_t1);
    cudaGetSymbolAddress((void**)&t,   g_t);
    cudaGetSymbolAddress((void**)&mw,  g_mw);
    cudaGetSymbolAddress((void**)&vn,  g_vn);
    cudaGetSymbolAddress((void**)&vn2, g_vn2);
    cudaGetSymbolAddress((void**)&vn3, g_vn3);
    cudaGetSymbolAddress((void**)&wh,  g_wh);
    cudaGetSymbolAddress((void**)&wl,  g_wl);

    static bool attr_done = false;
    if (!attr_done) {
        cudaFuncSetAttribute(gemm_mma_kernel<false, true,  false, false>, cudaFuncAttributeMaxDynamicSharedMemorySize, GEMM_SMEM);
        cudaFuncSetAttribute(gemm_mma_kernel<false, false, true,  false>, cudaFuncAttributeMaxDynamicSharedMemorySize, GEMM_SMEM);
        cudaFuncSetAttribute(gemm_mma_kernel<true,  true,  false, false>, cudaFuncAttributeMaxDynamicSharedMemorySize, GEMM_SMEM);
        cudaFuncSetAttribute(gemm_mma_kernel<false, true,  false, true>,  cudaFuncAttributeMaxDynamicSharedMemorySize, GEMM_SMEM);
        attr_done = true;
    }

    const int WS = 256 * 256;   // weight slot stride

    // launches 1-3
    split_all_kernel<<<dim3(256, 6), 256>>>(W_emb, W_gcn, aW1, aW2, vW1, vW2);
    zero_cursor_kernel<<<TOTAL_NODES / 256, 256>>>();
    fill_kernel<<<EE / 256, 256>>>(esrc, edst);

    // launch 4: G1 emb (profiler lands here): h = x @ W_emb + b_emb
    gemm_mma_kernel<false, true, false, false><<<dim3(HH / 128, TOTAL_NODES / 64), 256, GEMM_SMEM>>>(
        x, wh + 0 * WS, wl + 0 * WS, b_emb, h, TOTAL_NODES, HH, INF_);

    // G2: hw = (h @ W_gcn) * rsqrt(1+deg[row])   (dinv computed inline)
    gemm_mma_kernel<false, false, true, false><<<dim3(HH / 128, TOTAL_NODES / 64), 256, GEMM_SMEM>>>(
        h, wh + 1 * WS, wl + 1 * WS, nullptr, hw, TOTAL_NODES, HH, HH);
    // gather: g = relu(dinv_d * (sum + self) + b_gcn)  (overwrites g_h)
    gather_gcn_kernel<<<TOTAL_NODES / 4, dim3(64, 4)>>>(b_gcn);

    // G3: t1 = relu(g @ aW1 + ab1)
    gemm_mma_kernel<true, true, false, false><<<dim3(HH / 128, TOTAL_NODES / 64), 256, GEMM_SMEM>>>(
        h, wh + 2 * WS, wl + 2 * WS, ab1, t1, TOTAL_NODES, HH, HH);
    // G4: t = t1 @ aW2 + ab2, with fused proto column sums
    gemm_mma_kernel<false, true, false, true><<<dim3(HH / 128, TOTAL_NODES / 64), 256, GEMM_SMEM>>>(
        t1, wh + 3 * WS, wl + 3 * WS, ab2, t, TOTAL_NODES, HH, HH);

    // attention: proto mean+norm, then att+mw
    pn_kernel<<<BG, 256>>>();
    att_mw_kernel<<<TOTAL_NODES * 32 / 256, 256>>>(ew);

    // vn = mw^T @ g (per graph) via mma, then vn MLP
    vn_mma_kernel<<<dim3(2, BG), 256>>>(mw, h, vn);
    gemm_mma_kernel<true, true, false, false><<<dim3(HH / 128, BG * VV / 64), 256, GEMM_SMEM>>>(
        vn, wh + 4 * WS, wl + 4 * WS, vb1, vn2, BG * VV, HH, HH);
    gemm_mma_kernel<false, true, false, false><<<dim3(HH / 128, BG * VV / 64), 256, GEMM_SMEM>>>(
        vn2, wh + 5 * WS, wl + 5 * WS, vb2, vn3, BG * VV, HH, HH);

    // fused readout (gf + m1 GEMM + out)
    readout_kernel<<<BG, 256>>>(mW1, mb1, mW2, mb2, out);
}